// round 16
// baseline (speedup 1.0000x reference)
#include <cuda_runtime.h>
#include <cuda_fp16.h>
#include <cstdint>

// FreqGrid triplane encoder. R16 = R15 (compile fix: <cstdint>) :
//  - staging phase precomputes, per point: packed half2 bilinear weights
//    (x2 output scale folded in), per-plane texel base offsets, and kd.
//    The gather loop is reduced to: 5 broadcast LDS.128 + 3 IADD + 12 LDG +
//    the irreducible blend/cos core.
//  - everything else identical to R14 (best: 68.1us): fp16 transposed grid
//    (48 MB, L2-resident), padded grid, half-warp per point, 2-stage plane
//    pipeline, PAIRS=8, __ldcs/__stcs streaming hints.

#define RR 256
#define CHN 128
#define PLANE_ELEMS (RR * RR)              // 65536
#define GT_ELEMS (3 * PLANE_ELEMS * CHN)   // 48 MB of halfs
#define GT_PAD (33024)                     // covers +row+texel overrun (zeroed)

__device__ __half g_grid_t[GT_ELEMS + GT_PAD];

#define PI_OVER_R 0.01227184630308513f     // pi/256
#define KC        0.006135923151542565f    // pi/512

// swizzled half-index for (spatial row s, channel ch) in a 64x128 tile
__device__ __forceinline__ int sw_idx(int s, int ch) {
    int chunk = (ch >> 3) ^ ((s >> 2) & 15);
    return s * 128 + (chunk << 3) + (ch & 7);
}

// ---------------------------------------------------------------------------
// Transpose + quantize: in[p][ch][s] -> g_grid_t[p][s][ch] (fp16)
// ---------------------------------------------------------------------------
__global__ void __launch_bounds__(256) transpose_kernel(const float* __restrict__ g) {
    __shared__ __half tile[64 * 128];
    const int p  = blockIdx.y;
    const int s0 = blockIdx.x << 6;
    const int tid = threadIdx.x;

    const float* in = g + (size_t)p * CHN * PLANE_ELEMS + s0;

    #pragma unroll
    for (int i = 0; i < 8; i++) {
        int u  = i * 256 + tid;
        int q  = u & 15;
        int ch = u >> 4;
        float4 f = __ldcs((const float4*)(in + (size_t)ch * PLANE_ELEMS + 4 * q));
        tile[sw_idx(4 * q + 0, ch)] = __float2half_rn(f.x);
        tile[sw_idx(4 * q + 1, ch)] = __float2half_rn(f.y);
        tile[sw_idx(4 * q + 2, ch)] = __float2half_rn(f.z);
        tile[sw_idx(4 * q + 3, ch)] = __float2half_rn(f.w);
    }
    __syncthreads();

    __half* outp = g_grid_t + (size_t)p * PLANE_ELEMS * CHN + (size_t)s0 * CHN;
    #pragma unroll
    for (int i = 0; i < 4; i++) {
        int u  = i * 256 + tid;
        int c8 = u & 15;
        int s  = u >> 4;
        int chunk = c8 ^ ((s >> 2) & 15);
        uint4 val = *(const uint4*)&tile[s * 128 + (chunk << 3)];
        *(uint4*)(outp + s * CHN + 8 * c8) = val;
    }
}

// ---------------------------------------------------------------------------
// Gather + basis: half-warp per point, lane owns output channel c = lane&15
// ---------------------------------------------------------------------------
__device__ __forceinline__ void load_corners(const uint4* __restrict__ gb,
                                             int off, uint4* v) {
    v[0] = __ldg(&gb[off]);
    v[1] = __ldg(&gb[off + 16]);       // +x texel
    v[2] = __ldg(&gb[off + 4096]);     // +y row
    v[3] = __ldg(&gb[off + 4112]);
}

// blend with pre-packed half2 weights (output x2 already folded in)
__device__ __forceinline__ void blend_plane2(const uint4* v, uint4 w,
                                             float kdd, const float* frh,
                                             float& acc0, float& acc1) {
    __half2 w00 = *(const __half2*)&w.x;
    __half2 w01 = *(const __half2*)&w.y;
    __half2 w10 = *(const __half2*)&w.z;
    __half2 w11 = *(const __half2*)&w.w;

    const __half2* c0 = (const __half2*)&v[0];
    const __half2* c1 = (const __half2*)&v[1];
    const __half2* c2 = (const __half2*)&v[2];
    const __half2* c3 = (const __half2*)&v[3];

    #pragma unroll
    for (int q = 0; q < 4; q++) {
        __half2 cf = __hmul2(w00, c0[q]);
        cf = __hfma2(w01, c1[q], cf);
        cf = __hfma2(w10, c2[q], cf);
        cf = __hfma2(w11, c3[q], cf);
        float2 f = __half22float2(cf);
        acc0 = fmaf(f.x, __cosf(kdd * frh[2 * q]),     acc0);
        acc1 = fmaf(f.y, __cosf(kdd * frh[2 * q + 1]), acc1);
    }
}

__device__ __forceinline__ unsigned int pack_w(float x) {
    __half2 h = __float2half2_rn(x);
    return *(const unsigned int*)&h;
}

template <int PAIRS>
__global__ void __launch_bounds__(256)
freqgrid_kernel(const float* __restrict__ coords,
                const float* __restrict__ freqs,
                float* __restrict__ out, int N) {
    // Per-point staged scalars for the block's 128 points:
    //   s_w[p][i]  : packed half2 bilinear weights of plane p (x2 folded in)
    //   s_kd[i]    : cosine args per axis
    //   s_off[i]   : per-plane texel base offsets (in uint4 units)
    __shared__ uint4  s_w0[128], s_w1[128], s_w2[128];
    __shared__ float4 s_kd[128];
    __shared__ int4   s_off[128];

    const int tid  = threadIdx.x;
    const int lane = tid & 31;
    const int sub  = lane >> 4;     // 0: point A, 1: point B
    const int cl   = lane & 15;     // output channel / uint4 slot
    const int wloc = tid >> 5;      // warp index within block (0..7)

    const int PTS_PER_WARP = 2 * PAIRS;                 // 16
    const int pbase = blockIdx.x * (8 * PTS_PER_WARP);  // block's first point

    if (tid < 128) {
        int n = min(pbase + tid, N - 1);
        float p0 = fmaf(__ldcs(&coords[3 * n + 0]), 127.5f, 127.5f);
        float p1 = fmaf(__ldcs(&coords[3 * n + 1]), 127.5f, 127.5f);
        float p2 = fmaf(__ldcs(&coords[3 * n + 2]), 127.5f, 127.5f);

        s_kd[tid] = make_float4(fmaf(p0, PI_OVER_R, KC),
                                fmaf(p1, PI_OVER_R, KC),
                                fmaf(p2, PI_OVER_R, KC), 0.0f);

        // plane a: (ix,iy)=(p1,p2); b: (p0,p2); c: (p0,p1)
        float ixs[3] = {p1, p0, p0};
        float iys[3] = {p2, p2, p1};
        int offs[3];
        #pragma unroll
        for (int d = 0; d < 3; d++) {
            int x0 = (int)ixs[d];
            int y0 = (int)iys[d];
            float wx = ixs[d] - (float)x0;
            float wy = iys[d] - (float)y0;
            // fold the final 2.0f output scale into the weights (exact in fp16)
            uint4 wp;
            wp.x = pack_w(2.0f * (1.0f - wx) * (1.0f - wy));
            wp.y = pack_w(2.0f * wx * (1.0f - wy));
            wp.z = pack_w(2.0f * (1.0f - wx) * wy);
            wp.w = pack_w(2.0f * wx * wy);
            if (d == 0) s_w0[tid] = wp;
            else if (d == 1) s_w1[tid] = wp;
            else s_w2[tid] = wp;
            offs[d] = (d * PLANE_ELEMS + (y0 << 8) + x0) << 4;
        }
        s_off[tid] = make_int4(offs[0], offs[1], offs[2], 0);
    }

    // Per-lane frequency constants for channels 8*cl + j
    float frh[8];
    #pragma unroll
    for (int j = 0; j < 8; j++) {
        float fq = __ldg(&freqs[8 * cl + j]);
        fq = fminf(fmaxf(fq, 0.0f), 1.0f);
        frh[j] = exp2f(fq * 8.0f) - 0.5f;
    }

    __syncthreads();

    const uint4* __restrict__ gb = (const uint4*)g_grid_t;   // texel = 16 uint4
    const int base0 = (blockIdx.x * 8 + wloc) * PTS_PER_WARP;

    #pragma unroll
    for (int t = 0; t < PAIRS; t++) {
        const int nb = base0 + 2 * t;
        if (nb >= N) return;
        const int n = min(nb + sub, N - 1);

        const int local = wloc * PTS_PER_WARP + 2 * t + sub;   // 0..127
        float4 kdv = s_kd[local];
        int4   ofv = s_off[local];

        float acc0 = 0.0f, acc1 = 0.0f;
        uint4 va[4], vb[4];

        // 2-deep software pipeline over the 3 planes; weights loaded
        // just-before-use so only one uint4 of weights is live at a time.
        load_corners(gb, ofv.x + cl, va);
        load_corners(gb, ofv.y + cl, vb);
        blend_plane2(va, s_w0[local], kdv.x, frh, acc0, acc1);
        load_corners(gb, ofv.z + cl, va);
        blend_plane2(vb, s_w1[local], kdv.y, frh, acc0, acc1);
        blend_plane2(va, s_w2[local], kdv.z, frh, acc0, acc1);

        if (nb + sub < N) {
            __stcs(&out[n * 16 + cl], acc0 + acc1);
        }
    }
}

// ---------------------------------------------------------------------------
// Harness entry
// ---------------------------------------------------------------------------
extern "C" void kernel_launch(void* const* d_in, const int* in_sizes, int n_in,
                              void* d_out, int out_size) {
    const float* coords = (const float*)d_in[0];
    const float* grid   = (const float*)d_in[1];
    const float* freqs  = (const float*)d_in[2];
    float* out = (float*)d_out;

    const int N = in_sizes[0] / 3;

    dim3 tg(PLANE_ELEMS / 64, 3);
    transpose_kernel<<<tg, 256>>>(grid);

    constexpr int PAIRS = 8;                       // 16 points per warp
    const int pts_per_warp = 2 * PAIRS;
    const int pts_per_block = 8 * pts_per_warp;    // 128
    const int blocks = (N + pts_per_block - 1) / pts_per_block;
    freqgrid_kernel<PAIRS><<<blocks, 256>>>(coords, freqs, out, N);
}